// round 8
// baseline (speedup 1.0000x reference)
#include <cuda_runtime.h>
#include <math.h>
#include <stdint.h>

#define NDIM     128
#define TABK     512
#define BMAXF    8.0f
#define INV_BMAX 0.125f
#define ATT_SCALE 0.08838834764831845f  // 1/sqrt(128)
#define MAX_GRAPHS 16384
#define NODES_MAX 192                    // resident-graph capacity (51KB avg, +9sigma)
#define CHN       48                     // nodes per load chunk (24KB)
#define NCHUNK    4

// -------- persistent device scratch (static allocation only) --------
__device__ float g_M[2][NDIM];               // Wq @ Wk^T
__device__ float g_Kb[2];                    // Wk @ bq
__device__ int   g_start[MAX_GRAPHS];        // per-graph node offsets
__device__ float g_psi[2][TABK + 1][NDIM];   // charge_embed table psi_j(beta)

__device__ __forceinline__ float silu_f(float z) {
    return z / (1.0f + expf(-z));
}
__device__ __forceinline__ float softplus_fast(float s) {
    return fmaxf(s, 0.0f) + __logf(1.0f + __expf(-fabsf(s)));
}
__device__ __forceinline__ uint32_t smem_u32(const void* p) {
    uint32_t a;
    asm("{ .reg .u64 t; cvta.to.shared.u64 t, %1; cvt.u32.u64 %0, t; }"
        : "=r"(a) : "l"(p));
    return a;
}
#define MBAR_INIT(mb, cnt) \
    asm volatile("mbarrier.init.shared.b64 [%0], %1;" :: "r"(mb), "r"(cnt) : "memory")
#define MBAR_EXPECT_TX(mb, bytes) \
    asm volatile("mbarrier.arrive.expect_tx.shared.b64 _, [%0], %1;" \
                 :: "r"(mb), "r"(bytes) : "memory")
#define BULK_G2S(dst, src, bytes, mb) \
    asm volatile("cp.async.bulk.shared::cta.global.mbarrier::complete_tx::bytes " \
                 "[%0], [%1], %2, [%3];" \
                 :: "r"(dst), "l"(src), "r"(bytes), "r"(mb) : "memory")
#define BULK_S2G(dstg, srcs, bytes) \
    asm volatile("cp.async.bulk.global.shared::cta.bulk_group [%0], [%1], %2;" \
                 :: "l"(dstg), "r"(srcs), "r"(bytes) : "memory")
#define MBAR_WAIT(mb, parity) do {                                             \
    asm volatile(                                                              \
        "{\n\t.reg .pred P;\n\t"                                               \
        "W%=:\n\t"                                                             \
        "mbarrier.try_wait.parity.acquire.cta.shared::cta.b64 P, [%0], %1, 0x989680;\n\t" \
        "@P bra.uni D%=;\n\t"                                                  \
        "bra.uni W%=;\n\t"                                                     \
        "D%=:\n\t}"                                                            \
        :: "r"(mb), "r"(parity) : "memory");                                   \
} while (0)

// ================= aux kernel: table | starts | prep (unchanged R6) =========
#define TPB_T 16
#define NTB   ((TABK + 1 + TPB_T - 1) / TPB_T)   // 33
#define SB    40

__global__ __launch_bounds__(256) void aux_kernel(
    const void* __restrict__ batch_raw, int ngraphs, int nnodes,
    const float* __restrict__ Wq, const float* __restrict__ bq,
    const float* __restrict__ Wk, const float* __restrict__ Wv,
    const float* __restrict__ W1, const float* __restrict__ b1,
    const float* __restrict__ W2, const float* __restrict__ b2) {
    int bid = blockIdx.x;
    int tid = threadIdx.x;

    if (bid < 2 * NTB) {
        if (tid >= 128) return;
        int j  = bid / NTB;
        int tb = bid - j * NTB;
        int n  = tid;
        float u2 = 0.f;
        #pragma unroll 8
        for (int ee = 0; ee < NDIM; ee++)
            u2 = fmaf(Wv[j * NDIM + ee], W1[ee * NDIM + n], u2);
        __shared__ float h1s[TPB_T][NDIM];
        float b1n = b1[n];
        #pragma unroll
        for (int tt = 0; tt < TPB_T; tt++) {
            int t = tb * TPB_T + tt;
            if (t > TABK) break;
            float x = (float)t / (float)TABK;
            float beta = BMAXF * x * x;
            h1s[tt][n] = silu_f(fmaf(beta, u2, b1n));
        }
        __syncthreads();
        float b2n = b2[n];
        float wv = Wv[j * NDIM + n];
        for (int tt = 0; tt < TPB_T; tt++) {
            int t = tb * TPB_T + tt;
            if (t > TABK) break;
            float y = 0.f;
            #pragma unroll 8
            for (int d = 0; d < NDIM; d++) y = fmaf(h1s[tt][d], W2[d * NDIM + n], y);
            float x = (float)t / (float)TABK;
            float beta = BMAXF * x * x;
            g_psi[j][t][n] = fmaf(beta, wv, silu_f(y + b2n));
        }
    } else if (bid < 2 * NTB + SB) {
        int g = (bid - 2 * NTB) * 256 + tid;
        if (g > ngraphs) return;
        const int* b32 = (const int*)batch_raw;
        int w = (nnodes >= 8) ? ((nnodes & ~1) - 6) : 0;
        bool is64 = (b32[w + 1] == 0) && (b32[w + 3] == 0) && (b32[w + 5] == 0);
        const long long* b64 = (const long long*)batch_raw;
        long long gv = (long long)g;
        int lo = 0, hi = nnodes;
        while (lo < hi) {
            int mid = (lo + hi) >> 1;
            long long val = is64 ? b64[mid] : (long long)b32[mid];
            if (val < gv) lo = mid + 1; else hi = mid;
        }
        g_start[g] = lo;
    } else {
        int j = tid >> 7, e = tid & 127;
        const float* wk = Wk + j * NDIM;
        float m = 0.f;
        #pragma unroll 8
        for (int d = 0; d < NDIM; d++) m = fmaf(Wq[e * NDIM + d], wk[d], m);
        g_M[j][e] = m;
        if (tid < 2) {
            float kb = 0.f;
            for (int d = 0; d < NDIM; d++) kb = fmaf(Wk[tid * NDIM + d], bq[d], kb);
            g_Kb[tid] = kb;
        }
    }
}

// ===== main: whole graph resident in SMEM; TMA in, TMA out; 128 thr/block ====
__global__ __launch_bounds__(128) void main_kernel(
    const float* __restrict__ ns, const float* __restrict__ charge,
    float* __restrict__ out, int ngraphs) {
    cudaGridDependencySynchronize();     // PDL wait on aux, before any access

    extern __shared__ __align__(16) unsigned char smraw[];
    unsigned long long* mbar = (unsigned long long*)smraw;            // 4 x 8B
    float* warpsum = (float*)(smraw + 32);                            // 4
    float* sm_attn = warpsum + 4;                                     // NODES_MAX
    float* buf     = sm_attn + NODES_MAX;                             // NODES_MAX*NDIM

    int tid  = threadIdx.x;
    int wid  = tid >> 5, lane = tid & 31;
    int l8   = tid & 7;                 // lane within 8-lane group
    int gid  = tid >> 3;                // group 0..15

    if (tid < NCHUNK) MBAR_INIT(smem_u32(&mbar[tid]), 1);
    __syncthreads();

    int g = blockIdx.x;
    if (g >= ngraphs) return;

    float q  = charge[g];
    float r0 = fmaxf(q, 0.f), r1 = fmaxf(-q, 0.f);
    float c0 = fminf(r0, 1.f), c1 = fminf(r1, 1.f);
    float cg = c0 * g_Kb[0] + c1 * g_Kb[1];
    int   jj = (q < 0.f) ? 1 : 0;
    float qb = fmaxf(r0, r1);
    int n0 = g_start[g], n1 = g_start[g + 1];
    int gsize = n1 - n0;
    if (gsize <= 0) return;

    // combined projection Mc = c0*M0 + c1*M1, this lane's 16-float slice
    float4 Mc[4];
    #pragma unroll
    for (int jc = 0; jc < 4; jc++) {
        int e = jc * 32 + l8 * 4;
        float4 a = *reinterpret_cast<const float4*>(&g_M[0][e]);
        float4 b = *reinterpret_cast<const float4*>(&g_M[1][e]);
        Mc[jc].x = c0 * a.x + c1 * b.x;
        Mc[jc].y = c0 * a.y + c1 * b.y;
        Mc[jc].z = c0 * a.z + c1 * b.z;
        Mc[jc].w = c0 * a.w + c1 * b.w;
    }

    if (gsize <= NODES_MAX) {
        // ================= RESIDENT PATH =================
        int nch = (gsize + CHN - 1) / CHN;
        if (tid == 0) {
            #pragma unroll
            for (int c = 0; c < NCHUNK; c++) {
                if (c >= nch) break;
                uint32_t bytes = (uint32_t)min(CHN, gsize - c * CHN) * (NDIM * 4);
                uint32_t mb = smem_u32(&mbar[c]);
                MBAR_EXPECT_TX(mb, bytes);
                BULK_G2S(smem_u32(&buf[c * CHN * NDIM]),
                         (const void*)(ns + (long)(n0 + c * CHN) * NDIM), bytes, mb);
            }
        }
        // ---- phase A: consume chunks as they arrive (no smem reuse) ----
        float acc = 0.f;
        for (int c = 0; c < nch; c++) {
            MBAR_WAIT(smem_u32(&mbar[c]), 0);
            #pragma unroll
            for (int it = 0; it < CHN / 16; it++) {
                int nl = c * CHN + it * 16 + gid;      // node-local index
                float s = 0.f;
                bool valid = nl < gsize;
                if (valid) {
                    const float* r = &buf[nl * NDIM + l8 * 4];
                    #pragma unroll
                    for (int jc = 0; jc < 4; jc++) {
                        float4 v = *reinterpret_cast<const float4*>(r + jc * 32);
                        s += v.x * Mc[jc].x + v.y * Mc[jc].y
                           + v.z * Mc[jc].z + v.w * Mc[jc].w;
                    }
                }
                s += __shfl_xor_sync(0xffffffffu, s, 1);
                s += __shfl_xor_sync(0xffffffffu, s, 2);
                s += __shfl_xor_sync(0xffffffffu, s, 4);
                if (valid && l8 == 0) {
                    float attn = softplus_fast((s + cg) * ATT_SCALE);
                    acc += attn;
                    sm_attn[nl] = attn;
                }
            }
        }
        #pragma unroll
        for (int o = 16; o > 0; o >>= 1) acc += __shfl_xor_sync(0xffffffffu, acc, o);
        if (lane == 0) warpsum[wid] = acc;
        __syncthreads();
        float inv = 1.0f / (warpsum[0] + warpsum[1] + warpsum[2] + warpsum[3]);

        // ---- phase B: all resident; compute in place ----
        for (int nl = gid; nl < gsize; nl += 16) {
            float attn = sm_attn[nl];
            float beta = attn * inv * qb;
            float tf = (float)TABK * sqrtf(beta * INV_BMAX);
            int idx = (int)tf;
            if (idx > TABK - 1) idx = TABK - 1;
            float f = tf - (float)idx;
            const float* pa = &g_psi[jj][idx][0];
            float* r = &buf[nl * NDIM];
            #pragma unroll
            for (int jc = 0; jc < 4; jc++) {
                int e = jc * 32 + l8 * 4;
                float4 v = *reinterpret_cast<const float4*>(r + e);
                float4 a = *reinterpret_cast<const float4*>(pa + e);
                float4 bb = *reinterpret_cast<const float4*>(pa + NDIM + e);
                float4 o4;
                o4.x = v.x + fmaf(f, bb.x - a.x, a.x);
                o4.y = v.y + fmaf(f, bb.y - a.y, a.y);
                o4.z = v.z + fmaf(f, bb.z - a.z, a.z);
                o4.w = v.w + fmaf(f, bb.w - a.w, a.w);
                *reinterpret_cast<float4*>(r + e) = o4;
            }
        }
        // ---- bulk store whole graph output ----
        asm volatile("fence.proxy.async.shared::cta;" ::: "memory");
        __syncthreads();
        if (tid == 0) {
            BULK_S2G((void*)(out + (long)n0 * NDIM), smem_u32(&buf[0]),
                     (uint32_t)gsize * (NDIM * 4));
            asm volatile("cp.async.bulk.commit_group;" ::: "memory");
            asm volatile("cp.async.bulk.wait_group 0;" ::: "memory");
        }
    } else {
        // ================= FALLBACK PATH (huge graph; ~never) =================
        float acc = 0.f;
        for (int base = n0; base < n1; base += 16) {
            int node = base + gid;
            float s = 0.f;
            bool valid = node < n1;
            if (valid) {
                const float* row = ns + (long)node * NDIM + l8 * 4;
                #pragma unroll
                for (int jc = 0; jc < 4; jc++) {
                    float4 v = *reinterpret_cast<const float4*>(row + jc * 32);
                    s += v.x * Mc[jc].x + v.y * Mc[jc].y + v.z * Mc[jc].z + v.w * Mc[jc].w;
                }
            }
            s += __shfl_xor_sync(0xffffffffu, s, 1);
            s += __shfl_xor_sync(0xffffffffu, s, 2);
            s += __shfl_xor_sync(0xffffffffu, s, 4);
            if (valid && l8 == 0) acc += softplus_fast((s + cg) * ATT_SCALE);
        }
        #pragma unroll
        for (int o = 16; o > 0; o >>= 1) acc += __shfl_xor_sync(0xffffffffu, acc, o);
        if (lane == 0) warpsum[wid] = acc;
        __syncthreads();
        float inv = 1.0f / (warpsum[0] + warpsum[1] + warpsum[2] + warpsum[3]);

        for (int base = n0; base < n1; base += 16) {
            int node = base + gid;
            if (node >= n1) continue;
            float s = 0.f;
            const float* row = ns + (long)node * NDIM + l8 * 4;
            #pragma unroll
            for (int jc = 0; jc < 4; jc++) {
                float4 v = __ldcs(reinterpret_cast<const float4*>(row + jc * 32));
                s += v.x * Mc[jc].x + v.y * Mc[jc].y + v.z * Mc[jc].z + v.w * Mc[jc].w;
            }
            s += __shfl_xor_sync(0xffffffffu, s, 1);
            s += __shfl_xor_sync(0xffffffffu, s, 2);
            s += __shfl_xor_sync(0xffffffffu, s, 4);
            float attn = softplus_fast((s + cg) * ATT_SCALE);
            float beta = attn * inv * qb;
            float tf = (float)TABK * sqrtf(beta * INV_BMAX);
            int idx = (int)tf;
            if (idx > TABK - 1) idx = TABK - 1;
            float f = tf - (float)idx;
            const float* pa = &g_psi[jj][idx][0];
            const float* rr = ns + (long)node * NDIM;
            float* orow = out + (long)node * NDIM;
            #pragma unroll
            for (int jc = 0; jc < 4; jc++) {
                int e = jc * 32 + l8 * 4;
                float4 v = __ldcs(reinterpret_cast<const float4*>(rr + e));
                float4 a = *reinterpret_cast<const float4*>(pa + e);
                float4 bb = *reinterpret_cast<const float4*>(pa + NDIM + e);
                float4 o4;
                o4.x = v.x + fmaf(f, bb.x - a.x, a.x);
                o4.y = v.y + fmaf(f, bb.y - a.y, a.y);
                o4.z = v.z + fmaf(f, bb.z - a.z, a.z);
                o4.w = v.w + fmaf(f, bb.w - a.w, a.w);
                __stcs(reinterpret_cast<float4*>(orow + e), o4);
            }
        }
    }
}

extern "C" void kernel_launch(void* const* d_in, const int* in_sizes, int n_in,
                              void* d_out, int out_size) {
    const float* ns     = (const float*)d_in[0];
    const float* charge = (const float*)d_in[1];
    const void*  batch  = (const void*) d_in[2];
    const float* Wq     = (const float*)d_in[3];
    const float* bq     = (const float*)d_in[4];
    const float* Wk     = (const float*)d_in[5];
    const float* Wv     = (const float*)d_in[6];
    const float* W1     = (const float*)d_in[7];
    const float* b1     = (const float*)d_in[8];
    const float* W2     = (const float*)d_in[9];
    const float* b2     = (const float*)d_in[10];
    float* out = (float*)d_out;

    int nnodes  = in_sizes[0] / NDIM;
    int ngraphs = in_sizes[1];

    aux_kernel<<<2 * NTB + SB + 1, 256>>>(batch, ngraphs, nnodes,
                                          Wq, bq, Wk, Wv, W1, b1, W2, b2);

    // dynamic smem: mbar(32) + warpsum(16) + attn(NODES_MAX*4) + buf
    size_t shmem = 32 + 16 + NODES_MAX * 4 + (size_t)NODES_MAX * NDIM * 4;
    static int configured = 0;
    if (!configured) {
        cudaFuncSetAttribute(main_kernel,
                             cudaFuncAttributeMaxDynamicSharedMemorySize,
                             (int)shmem);
        configured = 1;
    }

    cudaLaunchConfig_t cfg = {};
    cfg.gridDim  = dim3((unsigned)ngraphs, 1, 1);
    cfg.blockDim = dim3(128, 1, 1);
    cfg.dynamicSmemBytes = shmem;
    cfg.stream = 0;
    cudaLaunchAttribute attrs[1];
    attrs[0].id = cudaLaunchAttributeProgrammaticStreamSerialization;
    attrs[0].val.programmaticStreamSerializationAllowed = 1;
    cfg.attrs = attrs;
    cfg.numAttrs = 1;
    cudaLaunchKernelEx(&cfg, main_kernel, ns, charge, out, ngraphs);
}

// round 9
// speedup vs baseline: 1.0765x; 1.0765x over previous
#include <cuda_runtime.h>
#include <math.h>
#include <stdint.h>

#define NDIM     128
#define TABK     512
#define BMAXF    8.0f
#define INV_BMAX 0.125f
#define ATT_SCALE 0.08838834764831845f  // 1/sqrt(128)
#define MAX_GRAPHS 16384
#define CAP      1024                    // smem attn cache per graph (nodes)

// -------- persistent device scratch (static allocation only) --------
__device__ float g_M[2][NDIM];               // Wq @ Wk^T
__device__ float g_Kb[2];                    // Wk @ bq
__device__ int   g_start[MAX_GRAPHS];        // per-graph node offsets
__device__ float g_psi[2][TABK + 1][NDIM];   // charge_embed table psi_j(beta)

__device__ __forceinline__ float silu_f(float z) {
    return z / (1.0f + expf(-z));
}
__device__ __forceinline__ float softplus_fast(float s) {
    return fmaxf(s, 0.0f) + __logf(1.0f + __expf(-fabsf(s)));
}

// ================= aux kernel: table | starts(scan) | prep =========
#define TPB_T 16
#define NTB   ((TABK + 1 + TPB_T - 1) / TPB_T)   // 33
#define SB    48

__global__ __launch_bounds__(256) void aux_kernel(
    const void* __restrict__ batch_raw, int ngraphs, int nnodes,
    const float* __restrict__ Wq, const float* __restrict__ bq,
    const float* __restrict__ Wk, const float* __restrict__ Wv,
    const float* __restrict__ W1, const float* __restrict__ b1,
    const float* __restrict__ W2, const float* __restrict__ b2) {
    int bid = blockIdx.x;
    int tid = threadIdx.x;

    if (bid < 2 * NTB) {
        // ---------------- table role ----------------
        if (tid >= 128) return;
        int j  = bid / NTB;
        int tb = bid - j * NTB;
        int n  = tid;
        float u2 = 0.f;
        #pragma unroll 8
        for (int ee = 0; ee < NDIM; ee++)
            u2 = fmaf(Wv[j * NDIM + ee], W1[ee * NDIM + n], u2);
        __shared__ float h1s[TPB_T][NDIM];
        float b1n = b1[n];
        #pragma unroll
        for (int tt = 0; tt < TPB_T; tt++) {
            int t = tb * TPB_T + tt;
            if (t > TABK) break;
            float x = (float)t / (float)TABK;
            float beta = BMAXF * x * x;
            h1s[tt][n] = silu_f(fmaf(beta, u2, b1n));
        }
        __syncthreads();
        float b2n = b2[n];
        float wv = Wv[j * NDIM + n];
        for (int tt = 0; tt < TPB_T; tt++) {
            int t = tb * TPB_T + tt;
            if (t > TABK) break;
            float y = 0.f;
            #pragma unroll 8
            for (int d = 0; d < NDIM; d++) y = fmaf(h1s[tt][d], W2[d * NDIM + n], y);
            float x = (float)t / (float)TABK;
            float beta = BMAXF * x * x;
            g_psi[j][t][n] = fmaf(beta, wv, silu_f(y + b2n));
        }
    } else if (bid < 2 * NTB + SB) {
        // ---------------- starts role: boundary scan ----------------
        const int* b32 = (const int*)batch_raw;
        int w = (nnodes >= 8) ? ((nnodes & ~1) - 6) : 0;
        bool is64 = (b32[w + 1] == 0) && (b32[w + 3] == 0) && (b32[w + 5] == 0);
        const long long* b64 = (const long long*)batch_raw;
        int nthr = SB * 256;
        int gt = (bid - 2 * NTB) * 256 + tid;
        for (int i = gt; i < nnodes; i += nthr) {
            int cur = is64 ? (int)b64[i] : b32[i];
            int nxt = (i + 1 < nnodes) ? (is64 ? (int)b64[i + 1] : b32[i + 1])
                                       : ngraphs;
            if (i == 0)
                for (int G = 0; G <= cur; G++) g_start[G] = 0;
            for (int G = cur + 1; G <= nxt; G++) g_start[G] = i + 1;
        }
    } else {
        // ---------------- prep role (M, Kb) ----------------
        int j = tid >> 7, e = tid & 127;
        const float* wk = Wk + j * NDIM;
        float m = 0.f;
        #pragma unroll 8
        for (int d = 0; d < NDIM; d++) m = fmaf(Wq[e * NDIM + d], wk[d], m);
        g_M[j][e] = m;
        if (tid < 2) {
            float kb = 0.f;
            for (int d = 0; d < NDIM; d++) kb = fmaf(Wk[tid * NDIM + d], bq[d], kb);
            g_Kb[tid] = kb;
        }
    }
}

// ===== main: 1 graph / 128-thread block (R6 structure, new cache policy) ====
#define NW  4
#define NPB (NW * 8)   // phase A: 8 nodes per warp per iteration
#define NPB_B (NW * 4) // phase B: 4 nodes per warp per iteration

__global__ __launch_bounds__(128, 8) void main_kernel(
    const float* __restrict__ ns, const float* __restrict__ charge,
    float* __restrict__ out, int ngraphs) {
    cudaGridDependencySynchronize();   // PDL wait on aux, before any access

    int tid  = threadIdx.x;
    int wid  = tid >> 5, lane = tid & 31;
    int l8   = lane & 7;
    int grp  = lane >> 3;
    __shared__ float warpsum[NW];
    __shared__ float sm_attn[CAP];

    int g = blockIdx.x;
    if (g >= ngraphs) return;

    float q  = charge[g];
    float r0 = fmaxf(q, 0.f), r1 = fmaxf(-q, 0.f);
    float c0 = fminf(r0, 1.f), c1 = fminf(r1, 1.f);
    float cg = c0 * g_Kb[0] + c1 * g_Kb[1];
    int   jj = (q < 0.f) ? 1 : 0;
    float qb = fmaxf(r0, r1);
    int n0 = g_start[g], n1 = g_start[g + 1];

    // combined projection Mc = c0*M0 + c1*M1, this lane's 16-float slice
    float4 Mc[4];
    #pragma unroll
    for (int jc = 0; jc < 4; jc++) {
        int e = jc * 32 + l8 * 4;
        float4 a = *reinterpret_cast<const float4*>(&g_M[0][e]);
        float4 b = *reinterpret_cast<const float4*>(&g_M[1][e]);
        Mc[jc].x = c0 * a.x + c1 * b.x;
        Mc[jc].y = c0 * a.y + c1 * b.y;
        Mc[jc].z = c0 * a.z + c1 * b.z;
        Mc[jc].w = c0 * a.w + c1 * b.w;
    }

    // ---- phase A: 2 nodes per 8-lane group per iter; loads front-batched ----
    float acc = 0.f;
    for (int base = n0; base < n1; base += NPB) {
        int nd0 = base + wid * 8 + grp * 2;
        int nd1 = nd0 + 1;
        bool v0 = nd0 < n1, v1 = nd1 < n1;
        float4 va[4], vb[4];
        const float* ra = ns + (long)nd0 * NDIM + l8 * 4;
        const float* rb = ns + (long)nd1 * NDIM + l8 * 4;
        #pragma unroll
        for (int jc = 0; jc < 4; jc++)
            va[jc] = v0 ? *reinterpret_cast<const float4*>(ra + jc * 32)
                        : make_float4(0.f, 0.f, 0.f, 0.f);
        #pragma unroll
        for (int jc = 0; jc < 4; jc++)
            vb[jc] = v1 ? *reinterpret_cast<const float4*>(rb + jc * 32)
                        : make_float4(0.f, 0.f, 0.f, 0.f);
        float s0 = 0.f, s1 = 0.f;
        #pragma unroll
        for (int jc = 0; jc < 4; jc++) {
            s0 += va[jc].x * Mc[jc].x + va[jc].y * Mc[jc].y
                + va[jc].z * Mc[jc].z + va[jc].w * Mc[jc].w;
            s1 += vb[jc].x * Mc[jc].x + vb[jc].y * Mc[jc].y
                + vb[jc].z * Mc[jc].z + vb[jc].w * Mc[jc].w;
        }
        s0 += __shfl_xor_sync(0xffffffffu, s0, 1);
        s1 += __shfl_xor_sync(0xffffffffu, s1, 1);
        s0 += __shfl_xor_sync(0xffffffffu, s0, 2);
        s1 += __shfl_xor_sync(0xffffffffu, s1, 2);
        s0 += __shfl_xor_sync(0xffffffffu, s0, 4);
        s1 += __shfl_xor_sync(0xffffffffu, s1, 4);
        if (l8 == 0) {
            if (v0) {
                float a0 = softplus_fast((s0 + cg) * ATT_SCALE);
                acc += a0;
                int li = nd0 - n0;
                if (li < CAP) sm_attn[li] = a0;
            }
            if (v1) {
                float a1 = softplus_fast((s1 + cg) * ATT_SCALE);
                acc += a1;
                int li = nd1 - n0;
                if (li < CAP) sm_attn[li] = a1;
            }
        }
    }
    #pragma unroll
    for (int o = 16; o > 0; o >>= 1) acc += __shfl_xor_sync(0xffffffffu, acc, o);
    if (lane == 0) warpsum[wid] = acc;
    __syncthreads();
    float asum = warpsum[0] + warpsum[1] + warpsum[2] + warpsum[3];
    float inv = 1.0f / asum;

    // ---- phase B: NORMAL loads (L1/L2 hits), streaming stores only ----
    for (int base = n0; base < n1; base += NPB_B) {
        int node = base + wid * 4 + grp;
        if (node >= n1) continue;
        int li = node - n0;
        float attn;
        if (li < CAP) {
            attn = sm_attn[li];
        } else {
            float s = 0.f;
            const float* row = ns + (long)node * NDIM + l8 * 4;
            #pragma unroll
            for (int jc = 0; jc < 4; jc++) {
                float4 v = *reinterpret_cast<const float4*>(row + jc * 32);
                s += v.x * Mc[jc].x + v.y * Mc[jc].y + v.z * Mc[jc].z + v.w * Mc[jc].w;
            }
            s += __shfl_xor_sync(0xffffffffu, s, 1);
            s += __shfl_xor_sync(0xffffffffu, s, 2);
            s += __shfl_xor_sync(0xffffffffu, s, 4);
            attn = softplus_fast((s + cg) * ATT_SCALE);
        }
        float beta = attn * inv * qb;
        float tf = (float)TABK * sqrtf(beta * INV_BMAX);
        int idx = (int)tf;
        if (idx > TABK - 1) idx = TABK - 1;
        float f = tf - (float)idx;
        const float* pa = &g_psi[jj][idx][0];
        const float* row = ns + (long)node * NDIM;
        float* orow = out + (long)node * NDIM;
        #pragma unroll
        for (int jc = 0; jc < 4; jc++) {
            int e = jc * 32 + l8 * 4;
            float4 v = *reinterpret_cast<const float4*>(row + e);
            float4 a = *reinterpret_cast<const float4*>(pa + e);
            float4 b = *reinterpret_cast<const float4*>(pa + NDIM + e);
            float4 o4;
            o4.x = v.x + fmaf(f, b.x - a.x, a.x);
            o4.y = v.y + fmaf(f, b.y - a.y, a.y);
            o4.z = v.z + fmaf(f, b.z - a.z, a.z);
            o4.w = v.w + fmaf(f, b.w - a.w, a.w);
            __stcs(reinterpret_cast<float4*>(orow + e), o4);
        }
    }
}

extern "C" void kernel_launch(void* const* d_in, const int* in_sizes, int n_in,
                              void* d_out, int out_size) {
    const float* ns     = (const float*)d_in[0];
    const float* charge = (const float*)d_in[1];
    const void*  batch  = (const void*) d_in[2];
    const float* Wq     = (const float*)d_in[3];
    const float* bq     = (const float*)d_in[4];
    const float* Wk     = (const float*)d_in[5];
    const float* Wv     = (const float*)d_in[6];
    const float* W1     = (const float*)d_in[7];
    const float* b1     = (const float*)d_in[8];
    const float* W2     = (const float*)d_in[9];
    const float* b2     = (const float*)d_in[10];
    float* out = (float*)d_out;

    int nnodes  = in_sizes[0] / NDIM;
    int ngraphs = in_sizes[1];

    aux_kernel<<<2 * NTB + SB + 1, 256>>>(batch, ngraphs, nnodes,
                                          Wq, bq, Wk, Wv, W1, b1, W2, b2);

    // PDL: main blocks prestage during aux
    cudaLaunchConfig_t cfg = {};
    cfg.gridDim  = dim3((unsigned)ngraphs, 1, 1);
    cfg.blockDim = dim3(128, 1, 1);
    cfg.dynamicSmemBytes = 0;
    cfg.stream = 0;
    cudaLaunchAttribute attrs[1];
    attrs[0].id = cudaLaunchAttributeProgrammaticStreamSerialization;
    attrs[0].val.programmaticStreamSerializationAllowed = 1;
    cfg.attrs = attrs;
    cfg.numAttrs = 1;
    cudaLaunchKernelEx(&cfg, main_kernel, ns, charge, out, ngraphs);
}

// round 10
// speedup vs baseline: 1.2717x; 1.1813x over previous
#include <cuda_runtime.h>
#include <math.h>
#include <stdint.h>

#define NDIM     128
#define TABK     256
#define BMAXF    8.0f
#define INV_BMAX 0.125f
#define ATT_SCALE 0.08838834764831845f  // 1/sqrt(128)
#define MAX_GRAPHS 16384
#define CAP      1024                    // smem attn cache per graph (nodes)

// -------- persistent device scratch (static allocation only) --------
__device__ float g_M[2][NDIM];               // Wq @ Wk^T
__device__ float g_Kb[2];                    // Wk @ bq
__device__ int   g_start[MAX_GRAPHS];        // per-graph node offsets
__device__ float g_psi[2][TABK + 1][NDIM];   // charge_embed table psi_j(beta)

__device__ __forceinline__ float silu_f(float z) {
    return z / (1.0f + expf(-z));
}
__device__ __forceinline__ float softplus_fast(float s) {
    return fmaxf(s, 0.0f) + __logf(1.0f + __expf(-fabsf(s)));
}

// ====== aux kernel: table (1 point/block) | starts (binary search) | prep ====
#define NTPTS (TABK + 1)       // 257 points per sign
#define NTAB2 (2 * NTPTS)      // 514 table blocks
#define SB    40

__global__ __launch_bounds__(256) void aux_kernel(
    const void* __restrict__ batch_raw, int ngraphs, int nnodes,
    const float* __restrict__ Wq, const float* __restrict__ bq,
    const float* __restrict__ Wk, const float* __restrict__ Wv,
    const float* __restrict__ W1, const float* __restrict__ b1,
    const float* __restrict__ W2, const float* __restrict__ b2) {
    int bid = blockIdx.x;
    int tid = threadIdx.x;

    if (bid < NTAB2) {
        // ---------------- table role: ONE (j, t) point per block ----------------
        if (tid >= 128) return;
        int j = bid / NTPTS;
        int t = bid - j * NTPTS;
        int n = tid;
        float x = (float)t / (float)TABK;
        float beta = BMAXF * x * x;

        // u2 = Wv[j,:] @ W1[:,n]  — 4-way split accumulators (short RAW chains)
        float ua = 0.f, ub = 0.f, uc = 0.f, ud = 0.f;
        #pragma unroll 4
        for (int ee = 0; ee < NDIM; ee += 4) {
            ua = fmaf(Wv[j * NDIM + ee + 0], W1[(ee + 0) * NDIM + n], ua);
            ub = fmaf(Wv[j * NDIM + ee + 1], W1[(ee + 1) * NDIM + n], ub);
            uc = fmaf(Wv[j * NDIM + ee + 2], W1[(ee + 2) * NDIM + n], uc);
            ud = fmaf(Wv[j * NDIM + ee + 3], W1[(ee + 3) * NDIM + n], ud);
        }
        float u2 = (ua + ub) + (uc + ud);

        __shared__ float h1s[NDIM];
        h1s[n] = silu_f(fmaf(beta, u2, b1[n]));
        __syncthreads();

        // y = h1s @ W2[:,n]  — 4-way split accumulators
        float ya = 0.f, yb = 0.f, yc = 0.f, yd = 0.f;
        #pragma unroll 4
        for (int d = 0; d < NDIM; d += 4) {
            ya = fmaf(h1s[d + 0], W2[(d + 0) * NDIM + n], ya);
            yb = fmaf(h1s[d + 1], W2[(d + 1) * NDIM + n], yb);
            yc = fmaf(h1s[d + 2], W2[(d + 2) * NDIM + n], yc);
            yd = fmaf(h1s[d + 3], W2[(d + 3) * NDIM + n], yd);
        }
        float y = (ya + yb) + (yc + yd);
        g_psi[j][t][n] = fmaf(beta, Wv[j * NDIM + n], silu_f(y + b2[n]));
    } else if (bid < NTAB2 + SB) {
        // ---------------- starts role: binary search (R6) ----------------
        int g = (bid - NTAB2) * 256 + tid;
        if (g > ngraphs) return;
        const int* b32 = (const int*)batch_raw;
        int w = (nnodes >= 8) ? ((nnodes & ~1) - 6) : 0;
        bool is64 = (b32[w + 1] == 0) && (b32[w + 3] == 0) && (b32[w + 5] == 0);
        const long long* b64 = (const long long*)batch_raw;
        long long gv = (long long)g;
        int lo = 0, hi = nnodes;
        while (lo < hi) {
            int mid = (lo + hi) >> 1;
            long long val = is64 ? b64[mid] : (long long)b32[mid];
            if (val < gv) lo = mid + 1; else hi = mid;
        }
        g_start[g] = lo;
    } else {
        // ---------------- prep role (M, Kb) ----------------
        int j = tid >> 7, e = tid & 127;
        const float* wk = Wk + j * NDIM;
        float m = 0.f;
        #pragma unroll 8
        for (int d = 0; d < NDIM; d++) m = fmaf(Wq[e * NDIM + d], wk[d], m);
        g_M[j][e] = m;
        if (tid < 2) {
            float kb = 0.f;
            for (int d = 0; d < NDIM; d++) kb = fmaf(Wk[tid * NDIM + d], bq[d], kb);
            g_Kb[tid] = kb;
        }
    }
}

// ===== main: byte-identical to R6 (best known: 179 us) =====
#define NW  4
#define NPB (NW * 8)   // phase A: 8 nodes per warp per iteration
#define NPB_B (NW * 4) // phase B: 4 nodes per warp per iteration

__global__ __launch_bounds__(128, 8) void main_kernel(
    const float* __restrict__ ns, const float* __restrict__ charge,
    float* __restrict__ out, int ngraphs) {
    // HW dependency wait on aux grid (PDL); before ANY global access
    cudaGridDependencySynchronize();

    int tid  = threadIdx.x;
    int wid  = tid >> 5, lane = tid & 31;
    int l8   = lane & 7;
    int grp  = lane >> 3;
    __shared__ float warpsum[NW];
    __shared__ float sm_attn[CAP];

    int g = blockIdx.x;
    if (g >= ngraphs) return;

    float q  = charge[g];
    float r0 = fmaxf(q, 0.f), r1 = fmaxf(-q, 0.f);
    float c0 = fminf(r0, 1.f), c1 = fminf(r1, 1.f);
    float cg = c0 * g_Kb[0] + c1 * g_Kb[1];
    int   jj = (q < 0.f) ? 1 : 0;
    float qb = fmaxf(r0, r1);
    int n0 = g_start[g], n1 = g_start[g + 1];

    // combined projection Mc = c0*M0 + c1*M1, this lane's 16-float slice
    float4 Mc[4];
    #pragma unroll
    for (int jc = 0; jc < 4; jc++) {
        int e = jc * 32 + l8 * 4;
        float4 a = *reinterpret_cast<const float4*>(&g_M[0][e]);
        float4 b = *reinterpret_cast<const float4*>(&g_M[1][e]);
        Mc[jc].x = c0 * a.x + c1 * b.x;
        Mc[jc].y = c0 * a.y + c1 * b.y;
        Mc[jc].z = c0 * a.z + c1 * b.z;
        Mc[jc].w = c0 * a.w + c1 * b.w;
    }

    // ---- phase A: 2 nodes per 8-lane group per iter; all loads front-batched --
    float acc = 0.f;
    for (int base = n0; base < n1; base += NPB) {
        int nd0 = base + wid * 8 + grp * 2;
        int nd1 = nd0 + 1;
        bool v0 = nd0 < n1, v1 = nd1 < n1;
        float4 va[4], vb[4];
        const float* ra = ns + (long)nd0 * NDIM + l8 * 4;
        const float* rb = ns + (long)nd1 * NDIM + l8 * 4;
        #pragma unroll
        for (int jc = 0; jc < 4; jc++)
            va[jc] = v0 ? *reinterpret_cast<const float4*>(ra + jc * 32)
                        : make_float4(0.f, 0.f, 0.f, 0.f);
        #pragma unroll
        for (int jc = 0; jc < 4; jc++)
            vb[jc] = v1 ? *reinterpret_cast<const float4*>(rb + jc * 32)
                        : make_float4(0.f, 0.f, 0.f, 0.f);
        float s0 = 0.f, s1 = 0.f;
        #pragma unroll
        for (int jc = 0; jc < 4; jc++) {
            s0 += va[jc].x * Mc[jc].x + va[jc].y * Mc[jc].y
                + va[jc].z * Mc[jc].z + va[jc].w * Mc[jc].w;
            s1 += vb[jc].x * Mc[jc].x + vb[jc].y * Mc[jc].y
                + vb[jc].z * Mc[jc].z + vb[jc].w * Mc[jc].w;
        }
        s0 += __shfl_xor_sync(0xffffffffu, s0, 1);
        s1 += __shfl_xor_sync(0xffffffffu, s1, 1);
        s0 += __shfl_xor_sync(0xffffffffu, s0, 2);
        s1 += __shfl_xor_sync(0xffffffffu, s1, 2);
        s0 += __shfl_xor_sync(0xffffffffu, s0, 4);
        s1 += __shfl_xor_sync(0xffffffffu, s1, 4);
        if (l8 == 0) {
            if (v0) {
                float a0 = softplus_fast((s0 + cg) * ATT_SCALE);
                acc += a0;
                int li = nd0 - n0;
                if (li < CAP) sm_attn[li] = a0;
            }
            if (v1) {
                float a1 = softplus_fast((s1 + cg) * ATT_SCALE);
                acc += a1;
                int li = nd1 - n0;
                if (li < CAP) sm_attn[li] = a1;
            }
        }
    }
    #pragma unroll
    for (int o = 16; o > 0; o >>= 1) acc += __shfl_xor_sync(0xffffffffu, acc, o);
    if (lane == 0) warpsum[wid] = acc;
    __syncthreads();
    float asum = warpsum[0] + warpsum[1] + warpsum[2] + warpsum[3];
    float inv = 1.0f / asum;

    // ---- phase B: table epilogue; evict-first reads, streaming stores ----
    for (int base = n0; base < n1; base += NPB_B) {
        int node = base + wid * 4 + grp;
        if (node >= n1) continue;
        int li = node - n0;
        float attn;
        if (li < CAP) {
            attn = sm_attn[li];
        } else {
            float s = 0.f;
            const float* row = ns + (long)node * NDIM + l8 * 4;
            #pragma unroll
            for (int jc = 0; jc < 4; jc++) {
                float4 v = __ldcs(reinterpret_cast<const float4*>(row + jc * 32));
                s += v.x * Mc[jc].x + v.y * Mc[jc].y + v.z * Mc[jc].z + v.w * Mc[jc].w;
            }
            s += __shfl_xor_sync(0xffffffffu, s, 1);
            s += __shfl_xor_sync(0xffffffffu, s, 2);
            s += __shfl_xor_sync(0xffffffffu, s, 4);
            attn = softplus_fast((s + cg) * ATT_SCALE);
        }
        float beta = attn * inv * qb;
        float tf = (float)TABK * sqrtf(beta * INV_BMAX);
        int idx = (int)tf;
        if (idx > TABK - 1) idx = TABK - 1;
        float f = tf - (float)idx;
        const float* pa = &g_psi[jj][idx][0];
        const float* row = ns + (long)node * NDIM;
        float* orow = out + (long)node * NDIM;
        #pragma unroll
        for (int jc = 0; jc < 4; jc++) {
            int e = jc * 32 + l8 * 4;
            float4 v = __ldcs(reinterpret_cast<const float4*>(row + e));
            float4 a = *reinterpret_cast<const float4*>(pa + e);
            float4 b = *reinterpret_cast<const float4*>(pa + NDIM + e);
            float4 o4;
            o4.x = v.x + fmaf(f, b.x - a.x, a.x);
            o4.y = v.y + fmaf(f, b.y - a.y, a.y);
            o4.z = v.z + fmaf(f, b.z - a.z, a.z);
            o4.w = v.w + fmaf(f, b.w - a.w, a.w);
            __stcs(reinterpret_cast<float4*>(orow + e), o4);
        }
    }
}

extern "C" void kernel_launch(void* const* d_in, const int* in_sizes, int n_in,
                              void* d_out, int out_size) {
    const float* ns     = (const float*)d_in[0];
    const float* charge = (const float*)d_in[1];
    const void*  batch  = (const void*) d_in[2];
    const float* Wq     = (const float*)d_in[3];
    const float* bq     = (const float*)d_in[4];
    const float* Wk     = (const float*)d_in[5];
    const float* Wv     = (const float*)d_in[6];
    const float* W1     = (const float*)d_in[7];
    const float* b1     = (const float*)d_in[8];
    const float* W2     = (const float*)d_in[9];
    const float* b2     = (const float*)d_in[10];
    float* out = (float*)d_out;

    int nnodes  = in_sizes[0] / NDIM;
    int ngraphs = in_sizes[1];

    aux_kernel<<<NTAB2 + SB + 1, 256>>>(batch, ngraphs, nnodes,
                                        Wq, bq, Wk, Wv, W1, b1, W2, b2);

    // PDL: main blocks prestage during aux
    cudaLaunchConfig_t cfg = {};
    cfg.gridDim  = dim3((unsigned)ngraphs, 1, 1);
    cfg.blockDim = dim3(128, 1, 1);
    cfg.dynamicSmemBytes = 0;
    cfg.stream = 0;
    cudaLaunchAttribute attrs[1];
    attrs[0].id = cudaLaunchAttributeProgrammaticStreamSerialization;
    attrs[0].val.programmaticStreamSerializationAllowed = 1;
    cfg.attrs = attrs;
    cfg.numAttrs = 1;
    cudaLaunchKernelEx(&cfg, main_kernel, ns, charge, out, ngraphs);
}